// round 12
// baseline (speedup 1.0000x reference)
#include <cuda_runtime.h>
#include <cuda_bf16.h>
#include <stdint.h>
#include <math.h>

#define BB 16
#define NN 4096
#define HH 512
#define NHEAD 8
#define MM 512
#define LNEPS 1e-5f

// ---------------- static scratch (no allocations allowed) ----------------
__device__ float g_ppart[BB * 32 * HH];
__device__ float g_pooled[BB * HH];
__device__ float g_gate[BB];
__device__ float g_sal[BB * NN];
__device__ int   g_cnt[BB];
__device__ int   g_idx[BB * MM];
__device__ int   g_map[BB * NN];
__device__ __nv_bfloat16 g_tokbf[(size_t)BB * NN * HH];
__device__ __nv_bfloat16 g_ipw[(size_t)3 * HH * HH];
__device__ __nv_bfloat16 g_opw[(size_t)HH * HH];
__device__ __nv_bfloat16 g_qkvbf[(size_t)BB * MM * 3 * HH];
__device__ __nv_bfloat16 g_attnbf[(size_t)BB * MM * HH];
__device__ float g_rel[(size_t)BB * MM * HH];

// ---------------- block reductions (128 threads = 4 warps) ----------------
__device__ __forceinline__ float bred_sum(float v, float* sh) {
#pragma unroll
    for (int o = 16; o; o >>= 1) v += __shfl_down_sync(0xffffffffu, v, o);
    int tid = threadIdx.x;
    if ((tid & 31) == 0) sh[tid >> 5] = v;
    __syncthreads();
    if (tid == 0) sh[0] = sh[0] + sh[1] + sh[2] + sh[3];
    __syncthreads();
    float r = sh[0];
    __syncthreads();
    return r;
}

// ---------------- BF16 helpers ----------------
__device__ __forceinline__ uint32_t pack_bf(float lo, float hi) {
    __nv_bfloat162 h = __floats2bfloat162_rn(lo, hi);
    return *reinterpret_cast<uint32_t*>(&h);
}

__device__ __forceinline__ void mma16(float* d, const uint32_t* a, const uint32_t* b) {
    asm volatile(
        "mma.sync.aligned.m16n8k16.row.col.f32.bf16.bf16.f32 "
        "{%0,%1,%2,%3}, {%4,%5,%6,%7}, {%8,%9}, {%0,%1,%2,%3};"
        : "+f"(d[0]), "+f"(d[1]), "+f"(d[2]), "+f"(d[3])
        : "r"(a[0]), "r"(a[1]), "r"(a[2]), "r"(a[3]), "r"(b[0]), "r"(b[1]));
}

__device__ __forceinline__ void ldsm4(uint32_t* r, uint32_t saddr) {
    asm volatile(
        "ldmatrix.sync.aligned.m8n8.x4.shared.b16 {%0,%1,%2,%3}, [%4];"
        : "=r"(r[0]), "=r"(r[1]), "=r"(r[2]), "=r"(r[3]) : "r"(saddr));
}

__device__ __forceinline__ void cp16(uint32_t daddr, const void* src) {
    asm volatile("cp.async.cg.shared.global [%0], [%1], 16;"
                 :: "r"(daddr), "l"(src));
}
__device__ __forceinline__ void cp_commit() {
    asm volatile("cp.async.commit_group;");
}

// ---------------- small kernels ----------------
__global__ void k_reset() {
    int t = blockIdx.x * blockDim.x + threadIdx.x;
    if (t < BB * NN) g_map[t] = -1;
    if (t < BB) g_cnt[t] = 0;
}

// convert weights to bf16 (once per launch, ~1.3MB)
__global__ void k_wconv(const float* __restrict__ ipw, const float* __restrict__ opw) {
    int t = blockIdx.x * 256 + threadIdx.x;
    const int NIP = 3 * HH * HH / 2;      // 393216 pairs
    const int NOP = HH * HH / 2;          // 131072 pairs
    if (t < NIP) {
        float2 v = ((const float2*)ipw)[t];
        ((uint32_t*)g_ipw)[t] = pack_bf(v.x, v.y);
    } else if (t < NIP + NOP) {
        int u = t - NIP;
        float2 v = ((const float2*)opw)[u];
        ((uint32_t*)g_opw)[u] = pack_bf(v.x, v.y);
    }
}

// fused pooled-partials + salience + bf16 token copy, one token pass.
__global__ void __launch_bounds__(512)
k_poolsal(const float* __restrict__ tok,
          const float* __restrict__ lg, const float* __restrict__ lb,
          const float* __restrict__ w, const float* __restrict__ wb) {
    __shared__ float tile[16][512];
    __shared__ float gw[512];
    __shared__ float red[32];
    __shared__ float sS[2];
    int b = blockIdx.x, c = blockIdx.y;
    int tid = threadIdx.x, lane = tid & 31, wid = tid >> 5;

    float gwv = lg[tid] * w[tid];
    float bwv = lb[tid] * w[tid];
    gw[tid] = gwv;
    {
        float a0 = gwv, a1 = bwv;
#pragma unroll
        for (int o = 16; o; o >>= 1) {
            a0 += __shfl_down_sync(0xffffffffu, a0, o);
            a1 += __shfl_down_sync(0xffffffffu, a1, o);
        }
        if (lane == 0) { red[wid] = a0; red[wid + 16] = a1; }
    }
    __syncthreads();
    if (tid == 0) {
        float s0 = 0.f, s1 = 0.f;
#pragma unroll
        for (int k = 0; k < 16; k++) { s0 += red[k]; s1 += red[k + 16]; }
        sS[0] = s0; sS[1] = s1;
    }
    __syncthreads();
    float Sgw = sS[0], S2 = sS[1];

    const float* p = tok + ((size_t)(b * NN + c * 128)) * HH + tid;
    float pool = 0.f;

    for (int t8 = 0; t8 < 8; t8++) {
#pragma unroll
        for (int r = 0; r < 16; r++) {
            size_t row = (size_t)(b * NN + c * 128 + t8 * 16 + r);
            float x = p[(size_t)(t8 * 16 + r) * HH];
            tile[r][tid] = x;
            pool += x;
            g_tokbf[row * HH + tid] = __float2bfloat16(x);
        }
        __syncthreads();
        {
            float Sx = 0.f, Sxx = 0.f, Sxg = 0.f;
#pragma unroll
            for (int i = 0; i < 16; i++) {
                float x = tile[wid][lane + 32 * i];
                Sx += x; Sxx += x * x; Sxg += x * gw[lane + 32 * i];
            }
#pragma unroll
            for (int o = 16; o; o >>= 1) {
                Sx  += __shfl_down_sync(0xffffffffu, Sx, o);
                Sxx += __shfl_down_sync(0xffffffffu, Sxx, o);
                Sxg += __shfl_down_sync(0xffffffffu, Sxg, o);
            }
            if (lane == 0) {
                float mean = Sx * (1.f / HH);
                float var = Sxx * (1.f / HH) - mean * mean;
                float rstd = rsqrtf(var + LNEPS);
                g_sal[b * NN + c * 128 + t8 * 16 + wid] =
                    rstd * (Sxg - mean * Sgw) + S2 + wb[0];
            }
        }
        __syncthreads();
    }
    g_ppart[(b * 32 + c) * HH + tid] = pool;
}

__global__ void k_pool2() {
    int b = blockIdx.x, h = threadIdx.x;
    float s = 0.f;
#pragma unroll
    for (int c = 0; c < 32; c++) s += g_ppart[(b * 32 + c) * HH + h];
    g_pooled[b * HH + h] = s * (1.f / NN);
}

__global__ void k_gate(const float* __restrict__ lg, const float* __restrict__ lb,
                       const float* __restrict__ w, const float* __restrict__ wb) {
    __shared__ float sh[4];
    int b = blockIdx.x, tid = threadIdx.x;
    const float* x = g_pooled + b * HH;
    float v0 = x[tid], v1 = x[tid + 128], v2 = x[tid + 256], v3 = x[tid + 384];
    float s = bred_sum(v0 + v1 + v2 + v3, sh);
    float q = bred_sum(v0 * v0 + v1 * v1 + v2 * v2 + v3 * v3, sh);
    float mean = s * (1.f / HH);
    float var = q * (1.f / HH) - mean * mean;
    float rstd = rsqrtf(var + LNEPS);
    float d = ((v0 - mean) * rstd * lg[tid] + lb[tid]) * w[tid]
            + ((v1 - mean) * rstd * lg[tid + 128] + lb[tid + 128]) * w[tid + 128]
            + ((v2 - mean) * rstd * lg[tid + 256] + lb[tid + 256]) * w[tid + 256]
            + ((v3 - mean) * rstd * lg[tid + 384] + lb[tid + 384]) * w[tid + 384];
    d = bred_sum(d, sh);
    if (tid == 0) g_gate[b] = 1.f / (1.f + expf(-(d + wb[0])));
}

__global__ void k_topk() {
    __shared__ float sh[NN];
    int b = blockIdx.x;
    for (int j = threadIdx.x; j < NN; j += 256) sh[j] = g_sal[b * NN + j];
    __syncthreads();
    int i = blockIdx.y * 256 + threadIdx.x;
    float si = sh[i];
    int cnt = 0;
    for (int j = 0; j < NN; j++) {
        float sj = sh[j];
        cnt += (sj > si) || (sj == si && j < i);
    }
    if (cnt < MM) {
        int p = atomicAdd(&g_cnt[b], 1);
        g_idx[b * MM + p] = i;
        g_map[b * NN + i] = p;
    }
}

// ---------------- pure-bf16 GEMM, cp.async 3-stage, ldmatrix ----------------
// C[m,n] = sum_k A[m,k]*B[n,k] + bias[n]; MT=NT=128; 256 thr; K multiple of 32.
// GATHER: A row r = g_tokbf[(r>>9)*NN + g_idx[r]]. OUTBF: write bf16 C.
#define GEMM_SMEM (6 * 10240)
template <int GATHER, int OUTBF>
__global__ void __launch_bounds__(256, 2)
k_gemm_bf(const __nv_bfloat16* __restrict__ A, const __nv_bfloat16* __restrict__ B,
          const float* __restrict__ bias, void* __restrict__ Cv,
          int K, int lda, int ldb, int ldc) {
    extern __shared__ uint32_t sm[];
    uint32_t* smA = sm;              // [3][128][20]
    uint32_t* smB = sm + 3 * 2560;   // [3][128][20]

    int m0 = blockIdx.y * 128, n0 = blockIdx.x * 128;
    int tid = threadIdx.x, lane = tid & 31, wid = tid >> 5;
    int wm = (wid >> 2) * 64, wn = (wid & 3) * 32;

    float acc[4][4][4];
#pragma unroll
    for (int i = 0; i < 4; i++)
#pragma unroll
        for (int j = 0; j < 4; j++) {
            acc[i][j][0] = 0.f; acc[i][j][1] = 0.f;
            acc[i][j][2] = 0.f; acc[i][j][3] = 0.f;
        }

    int lr2 = tid >> 1, hc = tid & 1;
    const __nv_bfloat16* arow;
    {
        int r = m0 + lr2;
        if (GATHER) arow = A + ((size_t)(r >> 9) * NN + g_idx[r]) * HH;
        else        arow = A + (size_t)r * lda;
    }
    const __nv_bfloat16* brow = B + (size_t)(n0 + lr2) * ldb;

    uint32_t smA_base = (uint32_t)__cvta_generic_to_shared(smA);
    uint32_t smB_base = (uint32_t)__cvta_generic_to_shared(smB);
    uint32_t aD = smA_base + lr2 * 80 + hc * 32;
    uint32_t bD = smB_base + lr2 * 80 + hc * 32;

    auto load_stage = [&](int kt, int st) {
        const char* as = (const char*)(arow + kt * 32 + hc * 16);
        const char* bs = (const char*)(brow + kt * 32 + hc * 16);
        cp16(aD + st * 10240, as);      cp16(aD + st * 10240 + 16, as + 16);
        cp16(bD + st * 10240, bs);      cp16(bD + st * 10240 + 16, bs + 16);
        cp_commit();
    };

    int mi = lane >> 3;
    int rA = (lane & 7) + ((mi & 1) << 3);
    int cA = (mi >> 1) << 2;
    int rB = (lane & 7) + ((mi >> 1) << 3);
    int cB = (mi & 1) << 2;

    int nk = K >> 5;
    load_stage(0, 0);
    load_stage(1, 1);

    for (int kt = 0; kt < nk; kt++) {
        int st = kt - (kt / 3) * 3;
        if (kt + 2 < nk) asm volatile("cp.async.wait_group 1;");
        else             asm volatile("cp.async.wait_group 0;");
        __syncthreads();
        if (kt + 2 < nk) load_stage(kt + 2, (kt + 2) - ((kt + 2) / 3) * 3);

        uint32_t a_base = smA_base + st * 10240;
        uint32_t b_base = smB_base + st * 10240;
#pragma unroll
        for (int ks = 0; ks < 2; ks++) {
            int kc = ks * 8;
            uint32_t af[4][4];
#pragma unroll
            for (int i = 0; i < 4; i++)
                ldsm4(af[i], a_base + (((wm + i * 16 + rA) * 20 + kc + cA) << 2));
            uint32_t bfr[4][2];
#pragma unroll
            for (int jp = 0; jp < 2; jp++) {
                uint32_t t4[4];
                ldsm4(t4, b_base + (((wn + jp * 16 + rB) * 20 + kc + cB) << 2));
                bfr[2 * jp][0] = t4[0]; bfr[2 * jp][1] = t4[1];
                bfr[2 * jp + 1][0] = t4[2]; bfr[2 * jp + 1][1] = t4[3];
            }
#pragma unroll
            for (int i = 0; i < 4; i++)
#pragma unroll
                for (int j = 0; j < 4; j++)
                    mma16(acc[i][j], af[i], bfr[j]);
        }
        __syncthreads();
    }

#pragma unroll
    for (int i = 0; i < 4; i++) {
        int r0 = m0 + wm + i * 16 + (lane >> 2);
#pragma unroll
        for (int j = 0; j < 4; j++) {
            int c0 = n0 + wn + j * 8 + ((lane & 3) << 1);
            float b0 = bias[c0], b1 = bias[c0 + 1];
            if (OUTBF) {
                __nv_bfloat16* C = (__nv_bfloat16*)Cv;
                *(uint32_t*)(C + (size_t)r0 * ldc + c0) =
                    pack_bf(acc[i][j][0] + b0, acc[i][j][1] + b1);
                *(uint32_t*)(C + (size_t)(r0 + 8) * ldc + c0) =
                    pack_bf(acc[i][j][2] + b0, acc[i][j][3] + b1);
            } else {
                float* C = (float*)Cv;
                *(float2*)(C + (size_t)r0 * ldc + c0) =
                    make_float2(acc[i][j][0] + b0, acc[i][j][1] + b1);
                *(float2*)(C + (size_t)(r0 + 8) * ldc + c0) =
                    make_float2(acc[i][j][2] + b0, acc[i][j][3] + b1);
            }
        }
    }
}

// ---------------- flash attention (bf16 qkv in, bf16 O out) ----------------
__global__ void __launch_bounds__(256, 2)
k_attn(const __nv_bfloat16* __restrict__ qkv, __nv_bfloat16* __restrict__ attn) {
    __shared__ __align__(16) uint32_t Ks[2][64][36];
    __shared__ __align__(16) uint32_t Vs[2][64][36];

    int z = blockIdx.x;
    int qt = z & 3, bh = z >> 2;
    int b = bh >> 3, h = bh & 7;
    int tid = threadIdx.x, lane = tid & 31, wid = tid >> 5;

    const __nv_bfloat16* base = qkv + (size_t)b * MM * 1536;
    const uint32_t* Qg = (const uint32_t*)(base + (size_t)(qt * 128) * 1536 + h * 64);
    const uint32_t* Kg = (const uint32_t*)(base + 512 + h * 64);
    const uint32_t* Vg = (const uint32_t*)(base + 1024 + h * 64);

    uint32_t* Ksf = &Ks[0][0][0];

    int mi = lane >> 3;
    int rA = (lane & 7) + ((mi & 1) << 3);
    int cA = (mi >> 1) << 2;
    int rB = (lane & 7) + ((mi >> 1) << 3);
    int cB = (mi & 1) << 2;

    // stage Q (128 rows x 32 u32)
    {
        int r = tid >> 1, ch = (tid & 1) * 16;
        const uint4* qp = (const uint4*)(Qg + (size_t)r * 768 + ch);
#pragma unroll
        for (int i = 0; i < 4; i++)
            *(uint4*)&Ksf[r * 36 + ch + i * 4] = qp[i];
    }
    __syncthreads();

    int wm = wid * 16;
    uint32_t aq[4][4];
    {
        uint32_t q_base = (uint32_t)__cvta_generic_to_shared(Ksf);
#pragma unroll
        for (int ks = 0; ks < 4; ks++)
            ldsm4(aq[ks], q_base + (((wm + rA) * 36 + ks * 8 + cA) << 2));
    }
    __syncthreads();

    int krow = tid >> 2, kcol = (tid & 3) * 8;
    int vdp = tid & 31, vpg = tid >> 5;
    uint4 kq0, kq1;
    uint32_t vreg[8];

    auto ldK = [&](int kt) {
        const uint4* kp = (const uint4*)(Kg + (size_t)(kt * 64 + krow) * 768 + kcol);
        kq0 = kp[0]; kq1 = kp[1];
    };
    auto stK = [&](int buf) {
        *(uint4*)&Ks[buf][krow][kcol]     = kq0;
        *(uint4*)&Ks[buf][krow][kcol + 4] = kq1;
    };
    auto ldV = [&](int kt) {
#pragma unroll
        for (int j = 0; j < 4; j++) {
            int p = vpg * 4 + j;
            uint32_t r0 = Vg[(size_t)(kt * 64 + 2 * p) * 768 + vdp];
            uint32_t r1 = Vg[(size_t)(kt * 64 + 2 * p + 1) * 768 + vdp];
            vreg[j * 2]     = __byte_perm(r0, r1, 0x5410);
            vreg[j * 2 + 1] = __byte_perm(r0, r1, 0x7632);
        }
    };
    auto stV = [&](int buf) {
#pragma unroll
        for (int j = 0; j < 4; j++) {
            int p = vpg * 4 + j;
            Vs[buf][vdp * 2][p]     = vreg[j * 2];
            Vs[buf][vdp * 2 + 1][p] = vreg[j * 2 + 1];
        }
    };

    float o[8][4] = {};
    float rs0 = 0.f, rs1 = 0.f;

    ldK(0); ldV(0); stK(0); stV(0);
    __syncthreads();

    for (int kt = 0; kt < 8; kt++) {
        int buf = kt & 1;
        if (kt < 7) { ldK(kt + 1); ldV(kt + 1); }
        uint32_t k_base = (uint32_t)__cvta_generic_to_shared(&Ks[buf][0][0]);
        uint32_t v_base = (uint32_t)__cvta_generic_to_shared(&Vs[buf][0][0]);

        float s[8][4] = {};
#pragma unroll
        for (int ks = 0; ks < 4; ks++) {
            uint32_t kf[8][2];
#pragma unroll
            for (int jp = 0; jp < 4; jp++) {
                uint32_t t4[4];
                ldsm4(t4, k_base + (((jp * 16 + rB) * 36 + ks * 8 + cB) << 2));
                kf[2 * jp][0] = t4[0]; kf[2 * jp][1] = t4[1];
                kf[2 * jp + 1][0] = t4[2]; kf[2 * jp + 1][1] = t4[3];
            }
#pragma unroll
            for (int j = 0; j < 8; j++)
                mma16(s[j], aq[ks], kf[j]);
        }
#pragma unroll
        for (int j = 0; j < 8; j++) {
            s[j][0] = __expf(s[j][0] * 0.125f);
            s[j][1] = __expf(s[j][1] * 0.125f);
            s[j][2] = __expf(s[j][2] * 0.125f);
            s[j][3] = __expf(s[j][3] * 0.125f);
            rs0 += s[j][0] + s[j][1];
            rs1 += s[j][2] + s[j][3];
        }
#pragma unroll
        for (int ks = 0; ks < 4; ks++) {
            uint32_t a[4] = {
                pack_bf(s[2 * ks][0],     s[2 * ks][1]),
                pack_bf(s[2 * ks][2],     s[2 * ks][3]),
                pack_bf(s[2 * ks + 1][0], s[2 * ks + 1][1]),
                pack_bf(s[2 * ks + 1][2], s[2 * ks + 1][3])};
            uint32_t vf[8][2];
#pragma unroll
            for (int jp = 0; jp < 4; jp++) {
                uint32_t t4[4];
                ldsm4(t4, v_base + (((jp * 16 + rB) * 36 + ks * 8 + cB) << 2));
                vf[2 * jp][0] = t4[0]; vf[2 * jp][1] = t4[1];
                vf[2 * jp + 1][0] = t4[2]; vf[2 * jp + 1][1] = t4[3];
            }
#pragma unroll
            for (int j = 0; j < 8; j++)
                mma16(o[j], a, vf[j]);
        }
        if (kt < 7) { stK(buf ^ 1); stV(buf ^ 1); }
        __syncthreads();
    }

    rs0 += __shfl_xor_sync(0xffffffffu, rs0, 1);
    rs0 += __shfl_xor_sync(0xffffffffu, rs0, 2);
    rs1 += __shfl_xor_sync(0xffffffffu, rs1, 1);
    rs1 += __shfl_xor_sync(0xffffffffu, rs1, 2);
    float i0 = 1.f / rs0, i1 = 1.f / rs1;

    uint32_t* Og = (uint32_t*)(attn + (size_t)b * MM * HH +
                               (size_t)(qt * 128) * HH + h * 64);
    int r = wm + (lane >> 2);
#pragma unroll
    for (int j = 0; j < 8; j++) {
        int c = j * 8 + (lane & 3) * 2;
        Og[(size_t)r * 256 + (c >> 1)]       = pack_bf(o[j][0] * i0, o[j][1] * i0);
        Og[(size_t)(r + 8) * 256 + (c >> 1)] = pack_bf(o[j][2] * i1, o[j][3] * i1);
    }
}

// y = LN(tok[idx] + rel), residual gathered straight from tokens
__global__ void k_lnres(const float* __restrict__ tok,
                        const float* __restrict__ lg, const float* __restrict__ lb) {
    __shared__ float sh[4];
    int t = blockIdx.x, tid = threadIdx.x;
    int b = t >> 9;
    float* r = g_rel + (size_t)t * HH;
    const float* s = tok + ((size_t)b * NN + g_idx[t]) * HH;
    float v0 = s[tid] + r[tid];
    float v1 = s[tid + 128] + r[tid + 128];
    float v2 = s[tid + 256] + r[tid + 256];
    float v3 = s[tid + 384] + r[tid + 384];
    float su = bred_sum(v0 + v1 + v2 + v3, sh);
    float q = bred_sum(v0 * v0 + v1 * v1 + v2 * v2 + v3 * v3, sh);
    float mean = su * (1.f / HH);
    float var = q * (1.f / HH) - mean * mean;
    float rstd = rsqrtf(var + LNEPS);
    r[tid]       = (v0 - mean) * rstd * lg[tid]       + lb[tid];
    r[tid + 128] = (v1 - mean) * rstd * lg[tid + 128] + lb[tid + 128];
    r[tid + 256] = (v2 - mean) * rstd * lg[tid + 256] + lb[tid + 256];
    r[tid + 384] = (v3 - mean) * rstd * lg[tid + 384] + lb[tid + 384];
}

// out[row] = tok[row] + (selected ? gate * rel[slot] : 0)
__global__ void k_final(const float* __restrict__ tok, float* __restrict__ out) {
    int row = blockIdx.x;
    int b = row >> 12;
    int m = g_map[row];
    int tid = threadIdx.x;
    const float4* src = (const float4*)(tok + (size_t)row * HH);
    float4* dst = (float4*)(out + (size_t)row * HH);
    float4 v = src[tid];
    if (m >= 0) {
        float gp = g_gate[b];
        const float4* r = (const float4*)(g_rel + ((size_t)b * MM + m) * HH);
        float4 rv = r[tid];
        v.x += gp * rv.x; v.y += gp * rv.y;
        v.z += gp * rv.z; v.w += gp * rv.w;
    }
    dst[tid] = v;
}

// ---------------- launch ----------------
extern "C" void kernel_launch(void* const* d_in, const int* in_sizes, int n_in,
                              void* d_out, int out_size) {
    const float* tok        = (const float*)d_in[0];
    const float* gate_ln_g  = (const float*)d_in[1];
    const float* gate_ln_b  = (const float*)d_in[2];
    const float* gate_w     = (const float*)d_in[3];
    const float* gate_b     = (const float*)d_in[4];
    const float* sal_ln_g   = (const float*)d_in[5];
    const float* sal_ln_b   = (const float*)d_in[6];
    const float* sal_w      = (const float*)d_in[7];
    const float* sal_b      = (const float*)d_in[8];
    const float* in_proj_w  = (const float*)d_in[9];
    const float* in_proj_b  = (const float*)d_in[10];
    const float* out_proj_w = (const float*)d_in[11];
    const float* out_proj_b = (const float*)d_in[12];
    const float* rel_ln_g   = (const float*)d_in[13];
    const float* rel_ln_b   = (const float*)d_in[14];
    float* out = (float*)d_out;

    void *p_tokbf_v, *p_ipw_v, *p_opw_v, *p_qkvbf_v, *p_attnbf_v;
    cudaGetSymbolAddress(&p_tokbf_v, g_tokbf);
    cudaGetSymbolAddress(&p_ipw_v, g_ipw);
    cudaGetSymbolAddress(&p_opw_v, g_opw);
    cudaGetSymbolAddress(&p_qkvbf_v, g_qkvbf);
    cudaGetSymbolAddress(&p_attnbf_v, g_attnbf);
    __nv_bfloat16* p_tokbf  = (__nv_bfloat16*)p_tokbf_v;
    __nv_bfloat16* p_ipw    = (__nv_bfloat16*)p_ipw_v;
    __nv_bfloat16* p_opw    = (__nv_bfloat16*)p_opw_v;
    __nv_bfloat16* p_qkvbf  = (__nv_bfloat16*)p_qkvbf_v;
    __nv_bfloat16* p_attnbf = (__nv_bfloat16*)p_attnbf_v;

    void* p_rel_v;
    cudaGetSymbolAddress(&p_rel_v, g_rel);
    float* p_rel = (float*)p_rel_v;

    cudaFuncSetAttribute(k_gemm_bf<1, 1>,
                         cudaFuncAttributeMaxDynamicSharedMemorySize, GEMM_SMEM);
    cudaFuncSetAttribute(k_gemm_bf<0, 0>,
                         cudaFuncAttributeMaxDynamicSharedMemorySize, GEMM_SMEM);

    k_reset<<<BB * NN / 256, 256>>>();
    k_wconv<<<2048, 256>>>(in_proj_w, out_proj_w);
    k_poolsal<<<dim3(BB, 32), 512>>>(tok, sal_ln_g, sal_ln_b, sal_w, sal_b);
    k_pool2<<<BB, 512>>>();
    k_gate<<<BB, 128>>>(gate_ln_g, gate_ln_b, gate_w, gate_b);
    k_topk<<<dim3(BB, NN / 256), 256>>>();

    // qkv = gather(tok_bf16)[sel] @ ipw^T + b : M=8192, N=1536, K=512, bf16 out
    k_gemm_bf<1, 1><<<dim3(12, 64, 1), 256, GEMM_SMEM>>>(
        p_tokbf, p_ipw, in_proj_b, p_qkvbf, HH, HH, HH, 3 * HH);

    // flash attention (bf16 in/out, S in registers)
    k_attn<<<BB * NHEAD * 4, 256>>>(p_qkvbf, p_attnbf);

    // rel = attn_bf @ opw^T + b : M=8192, N=512, K=512, fp32 out
    k_gemm_bf<0, 0><<<dim3(4, 64, 1), 256, GEMM_SMEM>>>(
        p_attnbf, p_opw, out_proj_b, p_rel, HH, HH, HH, HH);

    k_lnres<<<BB * MM, 128>>>(tok, rel_ln_g, rel_ln_b);
    k_final<<<BB * NN, 128>>>(tok, out);
}

// round 13
// speedup vs baseline: 1.4212x; 1.4212x over previous
#include <cuda_runtime.h>
#include <cuda_bf16.h>
#include <stdint.h>
#include <math.h>

#define BB 16
#define NN 4096
#define HH 512
#define NHEAD 8
#define MM 512
#define LNEPS 1e-5f

// ---------------- static scratch (no allocations allowed) ----------------
__device__ float g_ppart[BB * 32 * HH];
__device__ float g_pooled[BB * HH];
__device__ float g_gate[BB];
__device__ float g_sal[BB * NN];
__device__ int   g_cnt[BB];
__device__ int   g_idx[BB * MM];
__device__ float g_qkv[(size_t)BB * MM * 3 * HH];
__device__ float g_attn[(size_t)BB * MM * HH];
__device__ float g_rel[(size_t)BB * MM * HH];

// ---------------- block reductions (128 threads = 4 warps) ----------------
__device__ __forceinline__ float bred_sum(float v, float* sh) {
#pragma unroll
    for (int o = 16; o; o >>= 1) v += __shfl_down_sync(0xffffffffu, v, o);
    int tid = threadIdx.x;
    if ((tid & 31) == 0) sh[tid >> 5] = v;
    __syncthreads();
    if (tid == 0) sh[0] = sh[0] + sh[1] + sh[2] + sh[3];
    __syncthreads();
    float r = sh[0];
    __syncthreads();
    return r;
}

// ---------------- small kernels ----------------
__global__ void k_reset() {
    int t = blockIdx.x * blockDim.x + threadIdx.x;
    if (t < BB) g_cnt[t] = 0;
}

// full-tensor copy out = tok (runs on forked stream, overlapped with compute)
__global__ void k_copy(const float* __restrict__ tok, float* __restrict__ out) {
    size_t i = (size_t)blockIdx.x * 256 + threadIdx.x;
    ((float4*)out)[i] = ((const float4*)tok)[i];
}

// fused pooled-partials + salience, one token pass, warp-per-token reduction.
// sal[n] = rstd*(Sxgw - mean*Sgw) + sum(lb*w) + wb
__global__ void __launch_bounds__(512)
k_poolsal(const float* __restrict__ tok,
          const float* __restrict__ lg, const float* __restrict__ lb,
          const float* __restrict__ w, const float* __restrict__ wb) {
    __shared__ float tile[16][512];
    __shared__ float gw[512];
    __shared__ float red[32];
    __shared__ float sS[2];
    int b = blockIdx.x, c = blockIdx.y;
    int tid = threadIdx.x, lane = tid & 31, wid = tid >> 5;

    float gwv = lg[tid] * w[tid];
    float bwv = lb[tid] * w[tid];
    gw[tid] = gwv;
    {
        float a0 = gwv, a1 = bwv;
#pragma unroll
        for (int o = 16; o; o >>= 1) {
            a0 += __shfl_down_sync(0xffffffffu, a0, o);
            a1 += __shfl_down_sync(0xffffffffu, a1, o);
        }
        if (lane == 0) { red[wid] = a0; red[wid + 16] = a1; }
    }
    __syncthreads();
    if (tid == 0) {
        float s0 = 0.f, s1 = 0.f;
#pragma unroll
        for (int k = 0; k < 16; k++) { s0 += red[k]; s1 += red[k + 16]; }
        sS[0] = s0; sS[1] = s1;
    }
    __syncthreads();
    float Sgw = sS[0], S2 = sS[1];

    const float* p = tok + ((size_t)(b * NN + c * 128)) * HH + tid;
    float pool = 0.f;

    for (int t8 = 0; t8 < 8; t8++) {
#pragma unroll
        for (int r = 0; r < 16; r++) {
            float x = p[(size_t)(t8 * 16 + r) * HH];
            tile[r][tid] = x;
            pool += x;
        }
        __syncthreads();
        {
            float Sx = 0.f, Sxx = 0.f, Sxg = 0.f;
#pragma unroll
            for (int i = 0; i < 16; i++) {
                float x = tile[wid][lane + 32 * i];
                Sx += x; Sxx += x * x; Sxg += x * gw[lane + 32 * i];
            }
#pragma unroll
            for (int o = 16; o; o >>= 1) {
                Sx  += __shfl_down_sync(0xffffffffu, Sx, o);
                Sxx += __shfl_down_sync(0xffffffffu, Sxx, o);
                Sxg += __shfl_down_sync(0xffffffffu, Sxg, o);
            }
            if (lane == 0) {
                float mean = Sx * (1.f / HH);
                float var = Sxx * (1.f / HH) - mean * mean;
                float rstd = rsqrtf(var + LNEPS);
                g_sal[b * NN + c * 128 + t8 * 16 + wid] =
                    rstd * (Sxg - mean * Sgw) + S2 + wb[0];
            }
        }
        __syncthreads();
    }
    g_ppart[(b * 32 + c) * HH + tid] = pool;
}

__global__ void k_pool2() {
    int b = blockIdx.x, h = threadIdx.x;
    float s = 0.f;
#pragma unroll
    for (int c = 0; c < 32; c++) s += g_ppart[(b * 32 + c) * HH + h];
    g_pooled[b * HH + h] = s * (1.f / NN);
}

__global__ void k_gate(const float* __restrict__ lg, const float* __restrict__ lb,
                       const float* __restrict__ w, const float* __restrict__ wb) {
    __shared__ float sh[4];
    int b = blockIdx.x, tid = threadIdx.x;
    const float* x = g_pooled + b * HH;
    float v0 = x[tid], v1 = x[tid + 128], v2 = x[tid + 256], v3 = x[tid + 384];
    float s = bred_sum(v0 + v1 + v2 + v3, sh);
    float q = bred_sum(v0 * v0 + v1 * v1 + v2 * v2 + v3 * v3, sh);
    float mean = s * (1.f / HH);
    float var = q * (1.f / HH) - mean * mean;
    float rstd = rsqrtf(var + LNEPS);
    float d = ((v0 - mean) * rstd * lg[tid] + lb[tid]) * w[tid]
            + ((v1 - mean) * rstd * lg[tid + 128] + lb[tid + 128]) * w[tid + 128]
            + ((v2 - mean) * rstd * lg[tid + 256] + lb[tid + 256]) * w[tid + 256]
            + ((v3 - mean) * rstd * lg[tid + 384] + lb[tid + 384]) * w[tid + 384];
    d = bred_sum(d, sh);
    if (tid == 0) g_gate[b] = 1.f / (1.f + expf(-(d + wb[0])));
}

__global__ void k_topk() {
    __shared__ float sh[NN];
    int b = blockIdx.x;
    for (int j = threadIdx.x; j < NN; j += 256) sh[j] = g_sal[b * NN + j];
    __syncthreads();
    int i = blockIdx.y * 256 + threadIdx.x;
    float si = sh[i];
    int cnt = 0;
    for (int j = 0; j < NN; j++) {
        float sj = sh[j];
        cnt += (sj > si) || (sj == si && j < i);
    }
    if (cnt < MM) {
        int p = atomicAdd(&g_cnt[b], 1);
        g_idx[b * MM + p] = i;
    }
}

// ---------------- BF16 mma / ldmatrix helpers ----------------
__device__ __forceinline__ uint32_t pack_bf(float lo, float hi) {
    __nv_bfloat162 h = __floats2bfloat162_rn(lo, hi);
    return *reinterpret_cast<uint32_t*>(&h);
}

__device__ __forceinline__ void mma16(float* d, const uint32_t* a, const uint32_t* b) {
    asm volatile(
        "mma.sync.aligned.m16n8k16.row.col.f32.bf16.bf16.f32 "
        "{%0,%1,%2,%3}, {%4,%5,%6,%7}, {%8,%9}, {%0,%1,%2,%3};"
        : "+f"(d[0]), "+f"(d[1]), "+f"(d[2]), "+f"(d[3])
        : "r"(a[0]), "r"(a[1]), "r"(a[2]), "r"(a[3]), "r"(b[0]), "r"(b[1]));
}

__device__ __forceinline__ void ldsm4(uint32_t* r, uint32_t saddr) {
    asm volatile(
        "ldmatrix.sync.aligned.m8n8.x4.shared.b16 {%0,%1,%2,%3}, [%4];"
        : "=r"(r[0]), "=r"(r[1]), "=r"(r[2]), "=r"(r[3]) : "r"(saddr));
}

// ---------------- BF16 tensor-core GEMM (double-buffered, ldmatrix) ----------------
// GATHER=1: A row r is tok[(r>>9)*NN + g_idx[r]].
// C[m,n] = scale * sum_k A[m,k]*B[n,k] + bias[n]
template <int MT, int NT, int BWM, int BWN, int GATHER>
__global__ void __launch_bounds__(256, 2)
k_gemm_bf(const float* __restrict__ A, const float* __restrict__ B,
          const float* __restrict__ bias, float* __restrict__ C,
          int K, int lda, int ldb, int ldc, float scale) {
    constexpr int WM = MT / BWM, WN = NT / BWN;
    constexpr int AM = WM / 16, BN = WN / 8;
    constexpr int NA = MT / 32, NB = NT / 32;
    __shared__ uint32_t As[2][MT][20];
    __shared__ uint32_t Bs[2][NT][20];

    int m0 = blockIdx.y * MT, n0 = blockIdx.x * NT;
    int tid = threadIdx.x, lane = tid & 31, wid = tid >> 5;
    int wm = (wid / BWN) * WM, wn = (wid % BWN) * WN;

    float acc[AM][BN][4];
#pragma unroll
    for (int i = 0; i < AM; i++)
#pragma unroll
        for (int j = 0; j < BN; j++) {
            acc[i][j][0] = 0.f; acc[i][j][1] = 0.f;
            acc[i][j][2] = 0.f; acc[i][j][3] = 0.f;
        }

    int lr = tid >> 3;
    int lk = (tid & 7) << 2;
    int lc = (tid & 7) << 1;

    int mi = lane >> 3;
    int rA = (lane & 7) + ((mi & 1) << 3);
    int cA = (mi >> 1) << 2;
    int rB = (lane & 7) + ((mi >> 1) << 3);
    int cB = (mi & 1) << 2;

    const float* arow[NA];
#pragma unroll
    for (int i = 0; i < NA; i++) {
        int r = m0 + lr + 32 * i;
        if (GATHER)
            arow[i] = A + ((size_t)(r >> 9) * NN + g_idx[r]) * HH;
        else
            arow[i] = A + (size_t)r * lda;
    }

    float4 ar[NA], br[NB];

    auto loadT = [&](int k0) {
#pragma unroll
        for (int i = 0; i < NA; i++)
            ar[i] = *(const float4*)(arow[i] + k0 + lk);
#pragma unroll
        for (int i = 0; i < NB; i++)
            br[i] = *(const float4*)(B + (long)(n0 + lr + 32 * i) * ldb + k0 + lk);
    };
    auto storeT = [&](int buf) {
#pragma unroll
        for (int i = 0; i < NA; i++) {
            As[buf][lr + 32 * i][lc]     = pack_bf(ar[i].x, ar[i].y);
            As[buf][lr + 32 * i][lc + 1] = pack_bf(ar[i].z, ar[i].w);
        }
#pragma unroll
        for (int i = 0; i < NB; i++) {
            Bs[buf][lr + 32 * i][lc]     = pack_bf(br[i].x, br[i].y);
            Bs[buf][lr + 32 * i][lc + 1] = pack_bf(br[i].z, br[i].w);
        }
    };

    int nk = K >> 5;
    loadT(0);
    storeT(0);
    __syncthreads();

    for (int kt = 0; kt < nk; kt++) {
        int buf = kt & 1;
        if (kt + 1 < nk) loadT((kt + 1) << 5);
        uint32_t a_base = (uint32_t)__cvta_generic_to_shared(&As[buf][0][0]);
        uint32_t b_base = (uint32_t)__cvta_generic_to_shared(&Bs[buf][0][0]);
#pragma unroll
        for (int ks = 0; ks < 2; ks++) {
            int kc = ks * 8;
            uint32_t af[AM][4];
#pragma unroll
            for (int i = 0; i < AM; i++)
                ldsm4(af[i], a_base + (((wm + i * 16 + rA) * 20 + kc + cA) << 2));
            uint32_t bfr[BN][2];
#pragma unroll
            for (int jp = 0; jp < BN / 2; jp++) {
                uint32_t t4[4];
                ldsm4(t4, b_base + (((wn + jp * 16 + rB) * 20 + kc + cB) << 2));
                bfr[2 * jp][0] = t4[0]; bfr[2 * jp][1] = t4[1];
                bfr[2 * jp + 1][0] = t4[2]; bfr[2 * jp + 1][1] = t4[3];
            }
#pragma unroll
            for (int i = 0; i < AM; i++)
#pragma unroll
                for (int j = 0; j < BN; j++)
                    mma16(acc[i][j], af[i], bfr[j]);
        }
        if (kt + 1 < nk) storeT(buf ^ 1);
        __syncthreads();
    }

#pragma unroll
    for (int i = 0; i < AM; i++) {
        int r0 = m0 + wm + i * 16 + (lane >> 2);
#pragma unroll
        for (int j = 0; j < BN; j++) {
            int c0 = n0 + wn + j * 8 + ((lane & 3) << 1);
            float b0 = 0.f, b1 = 0.f;
            if (bias) { b0 = bias[c0]; b1 = bias[c0 + 1]; }
            float2 o0, o1;
            o0.x = acc[i][j][0] * scale + b0;
            o0.y = acc[i][j][1] * scale + b1;
            o1.x = acc[i][j][2] * scale + b0;
            o1.y = acc[i][j][3] * scale + b1;
            *(float2*)(C + (long)r0 * ldc + c0) = o0;
            *(float2*)(C + (long)(r0 + 8) * ldc + c0) = o1;
        }
    }
}

// ---------------- flash attention (ldmatrix fragments) ----------------
__global__ void __launch_bounds__(256, 2)
k_attn(const float* __restrict__ qkv, float* __restrict__ attn) {
    __shared__ uint32_t Ks[2][64][36];
    __shared__ uint32_t Vs[2][64][36];

    int z = blockIdx.x;
    int qt = z & 3, bh = z >> 2;
    int b = bh >> 3, h = bh & 7;
    int tid = threadIdx.x, lane = tid & 31, wid = tid >> 5;

    const float* base = qkv + (size_t)b * MM * 1536;
    const float* Qg = base + (size_t)(qt * 128) * 1536 + h * 64;
    const float* Kg = base + 512 + h * 64;
    const float* Vg = base + 1024 + h * 64;

    uint32_t* Ksf = &Ks[0][0][0];

    int mi = lane >> 3;
    int rA = (lane & 7) + ((mi & 1) << 3);
    int cA = (mi >> 1) << 2;
    int rB = (lane & 7) + ((mi >> 1) << 3);
    int cB = (mi & 1) << 2;

    {
        int r = tid >> 1, ch = (tid & 1) * 32;
        const float* qp = Qg + (size_t)r * 1536 + ch;
        int o = r * 36 + ch / 2;
#pragma unroll
        for (int i = 0; i < 8; i++) {
            float4 v = *(const float4*)(qp + i * 4);
            Ksf[o + i * 2]     = pack_bf(v.x, v.y);
            Ksf[o + i * 2 + 1] = pack_bf(v.z, v.w);
        }
    }
    __syncthreads();

    int wm = wid * 16;
    uint32_t aq[4][4];
    {
        uint32_t q_base = (uint32_t)__cvta_generic_to_shared(Ksf);
#pragma unroll
        for (int ks = 0; ks < 4; ks++)
            ldsm4(aq[ks], q_base + (((wm + rA) * 36 + ks * 8 + cA) << 2));
    }
    __syncthreads();

    int krow = tid >> 2, kq = tid & 3;
    int vdp = tid & 31, vpg = tid >> 5;
    uint32_t kreg[8], vreg[8];

    auto ldK = [&](int kt) {
        const float* kp = Kg + (size_t)(kt * 64 + krow) * 1536 + kq * 16;
#pragma unroll
        for (int i = 0; i < 4; i++) {
            float4 v = *(const float4*)(kp + i * 4);
            kreg[i * 2]     = pack_bf(v.x, v.y);
            kreg[i * 2 + 1] = pack_bf(v.z, v.w);
        }
    };
    auto stK = [&](int buf) {
#pragma unroll
        for (int i = 0; i < 8; i++) Ks[buf][krow][kq * 8 + i] = kreg[i];
    };
    auto ldV = [&](int kt) {
#pragma unroll
        for (int j = 0; j < 4; j++) {
            int p = vpg * 4 + j;
            float2 v0 = *(const float2*)(Vg + (size_t)(kt * 64 + 2 * p) * 1536 + vdp * 2);
            float2 v1 = *(const float2*)(Vg + (size_t)(kt * 64 + 2 * p + 1) * 1536 + vdp * 2);
            vreg[j * 2]     = pack_bf(v0.x, v1.x);
            vreg[j * 2 + 1] = pack_bf(v0.y, v1.y);
        }
    };
    auto stV = [&](int buf) {
#pragma unroll
        for (int j = 0; j < 4; j++) {
            int p = vpg * 4 + j;
            Vs[buf][vdp * 2][p]     = vreg[j * 2];
            Vs[buf][vdp * 2 + 1][p] = vreg[j * 2 + 1];
        }
    };

    float o[8][4] = {};
    float rs0 = 0.f, rs1 = 0.f;

    ldK(0); ldV(0); stK(0); stV(0);
    __syncthreads();

    for (int kt = 0; kt < 8; kt++) {
        int buf = kt & 1;
        if (kt < 7) { ldK(kt + 1); ldV(kt + 1); }
        uint32_t k_base = (uint32_t)__cvta_generic_to_shared(&Ks[buf][0][0]);
        uint32_t v_base = (uint32_t)__cvta_generic_to_shared(&Vs[buf][0][0]);

        float s[8][4] = {};
#pragma unroll
        for (int ks = 0; ks < 4; ks++) {
            uint32_t kf[8][2];
#pragma unroll
            for (int jp = 0; jp < 4; jp++) {
                uint32_t t4[4];
                ldsm4(t4, k_base + (((jp * 16 + rB) * 36 + ks * 8 + cB) << 2));
                kf[2 * jp][0] = t4[0]; kf[2 * jp][1] = t4[1];
                kf[2 * jp + 1][0] = t4[2]; kf[2 * jp + 1][1] = t4[3];
            }
#pragma unroll
            for (int j = 0; j < 8; j++)
                mma16(s[j], aq[ks], kf[j]);
        }
#pragma unroll
        for (int j = 0; j < 8; j++) {
            s[j][0] = __expf(s[j][0] * 0.125f);
            s[j][1] = __expf(s[j][1] * 0.125f);
            s[j][2] = __expf(s[j][2] * 0.125f);
            s[j][3] = __expf(s[j][3] * 0.125f);
            rs0 += s[j][0] + s[j][1];
            rs1 += s[j][2] + s[j][3];
        }
#pragma unroll
        for (int ks = 0; ks < 4; ks++) {
            uint32_t a[4] = {
                pack_bf(s[2 * ks][0],     s[2 * ks][1]),
                pack_bf(s[2 * ks][2],     s[2 * ks][3]),
                pack_bf(s[2 * ks + 1][0], s[2 * ks + 1][1]),
                pack_bf(s[2 * ks + 1][2], s[2 * ks + 1][3])};
            uint32_t vf[8][2];
#pragma unroll
            for (int jp = 0; jp < 4; jp++) {
                uint32_t t4[4];
                ldsm4(t4, v_base + (((jp * 16 + rB) * 36 + ks * 8 + cB) << 2));
                vf[2 * jp][0] = t4[0]; vf[2 * jp][1] = t4[1];
                vf[2 * jp + 1][0] = t4[2]; vf[2 * jp + 1][1] = t4[3];
            }
#pragma unroll
            for (int j = 0; j < 8; j++)
                mma16(o[j], a, vf[j]);
        }
        if (kt < 7) { stK(buf ^ 1); stV(buf ^ 1); }
        __syncthreads();
    }

    rs0 += __shfl_xor_sync(0xffffffffu, rs0, 1);
    rs0 += __shfl_xor_sync(0xffffffffu, rs0, 2);
    rs1 += __shfl_xor_sync(0xffffffffu, rs1, 1);
    rs1 += __shfl_xor_sync(0xffffffffu, rs1, 2);
    float i0 = 1.f / rs0, i1 = 1.f / rs1;

    float* Og = attn + (size_t)b * MM * HH + (size_t)(qt * 128) * HH + h * 64;
    int r = wm + (lane >> 2);
#pragma unroll
    for (int j = 0; j < 8; j++) {
        int c = j * 8 + (lane & 3) * 2;
        *(float2*)(Og + (size_t)r * HH + c)       = make_float2(o[j][0] * i0, o[j][1] * i0);
        *(float2*)(Og + (size_t)(r + 8) * HH + c) = make_float2(o[j][2] * i1, o[j][3] * i1);
    }
}

// y = LN(tok[idx] + rel), residual gathered straight from tokens
__global__ void k_lnres(const float* __restrict__ tok,
                        const float* __restrict__ lg, const float* __restrict__ lb) {
    __shared__ float sh[4];
    int t = blockIdx.x, tid = threadIdx.x;
    int b = t >> 9;
    float* r = g_rel + (size_t)t * HH;
    const float* s = tok + ((size_t)b * NN + g_idx[t]) * HH;
    float v0 = s[tid] + r[tid];
    float v1 = s[tid + 128] + r[tid + 128];
    float v2 = s[tid + 256] + r[tid + 256];
    float v3 = s[tid + 384] + r[tid + 384];
    float su = bred_sum(v0 + v1 + v2 + v3, sh);
    float q = bred_sum(v0 * v0 + v1 * v1 + v2 * v2 + v3 * v3, sh);
    float mean = su * (1.f / HH);
    float var = q * (1.f / HH) - mean * mean;
    float rstd = rsqrtf(var + LNEPS);
    r[tid]       = (v0 - mean) * rstd * lg[tid]       + lb[tid];
    r[tid + 128] = (v1 - mean) * rstd * lg[tid + 128] + lb[tid + 128];
    r[tid + 256] = (v2 - mean) * rstd * lg[tid + 256] + lb[tid + 256];
    r[tid + 384] = (v3 - mean) * rstd * lg[tid + 384] + lb[tid + 384];
}

// out[selected row] += gate * rel   (out already holds tok via k_copy)
__global__ void k_scatter(float* __restrict__ out) {
    int t = blockIdx.x, tid = threadIdx.x;
    int b = t >> 9;
    float gp = g_gate[b];
    float4* dst = (float4*)(out + ((size_t)b * NN + g_idx[t]) * HH);
    const float4* r = (const float4*)(g_rel + (size_t)t * HH);
    float4 v = dst[tid];
    float4 rv = r[tid];
    v.x += gp * rv.x; v.y += gp * rv.y;
    v.z += gp * rv.z; v.w += gp * rv.w;
    dst[tid] = v;
}

// ---------------- launch ----------------
extern "C" void kernel_launch(void* const* d_in, const int* in_sizes, int n_in,
                              void* d_out, int out_size) {
    const float* tok        = (const float*)d_in[0];
    const float* gate_ln_g  = (const float*)d_in[1];
    const float* gate_ln_b  = (const float*)d_in[2];
    const float* gate_w     = (const float*)d_in[3];
    const float* gate_b     = (const float*)d_in[4];
    const float* sal_ln_g   = (const float*)d_in[5];
    const float* sal_ln_b   = (const float*)d_in[6];
    const float* sal_w      = (const float*)d_in[7];
    const float* sal_b      = (const float*)d_in[8];
    const float* in_proj_w  = (const float*)d_in[9];
    const float* in_proj_b  = (const float*)d_in[10];
    const float* out_proj_w = (const float*)d_in[11];
    const float* out_proj_b = (const float*)d_in[12];
    const float* rel_ln_g   = (const float*)d_in[13];
    const float* rel_ln_b   = (const float*)d_in[14];
    float* out = (float*)d_out;

    void *p_qkv_v, *p_attn_v, *p_rel_v;
    cudaGetSymbolAddress(&p_qkv_v, g_qkv);
    cudaGetSymbolAddress(&p_attn_v, g_attn);
    cudaGetSymbolAddress(&p_rel_v, g_rel);
    float* p_qkv = (float*)p_qkv_v;
    float* p_attn = (float*)p_attn_v;
    float* p_rel = (float*)p_rel_v;

    // fork a side stream for the big out=tok copy (overlaps the compute chain)
    cudaStream_t s2;
    cudaEvent_t eFork, eCopy;
    cudaStreamCreateWithFlags(&s2, cudaStreamNonBlocking);
    cudaEventCreateWithFlags(&eFork, cudaEventDisableTiming);
    cudaEventCreateWithFlags(&eCopy, cudaEventDisableTiming);

    cudaEventRecord(eFork, 0);
    cudaStreamWaitEvent(s2, eFork, 0);
    k_copy<<<(BB * NN * HH / 4) / 256, 256, 0, s2>>>(tok, out);
    cudaEventRecord(eCopy, s2);

    k_reset<<<1, 32>>>();
    k_poolsal<<<dim3(BB, 32), 512>>>(tok, sal_ln_g, sal_ln_b, sal_w, sal_b);
    k_pool2<<<BB, 512>>>();
    k_gate<<<BB, 128>>>(gate_ln_g, gate_ln_b, gate_w, gate_b);
    k_topk<<<dim3(BB, NN / 256), 256>>>();

    // qkv = gather(tok)[sel] @ in_proj_w^T + in_proj_b : M=8192, N=1536, K=512
    k_gemm_bf<128, 128, 2, 4, 1><<<dim3(12, 64, 1), 256>>>(
        tok, in_proj_w, in_proj_b, p_qkv, HH, HH, HH, 3 * HH, 1.f);

    // flash attention (S in registers)
    k_attn<<<BB * NHEAD * 4, 256>>>(p_qkv, p_attn);

    // rel = attn_out @ out_proj_w^T + out_proj_b : M=8192, N=512, K=512
    k_gemm_bf<128, 128, 2, 4, 0><<<dim3(4, 64, 1), 256>>>(
        p_attn, out_proj_w, out_proj_b, p_rel, HH, HH, HH, HH, 1.f);

    k_lnres<<<BB * MM, 128>>>(tok, rel_ln_g, rel_ln_b);

    // join: scatter needs the copy to be done
    cudaStreamWaitEvent(0, eCopy, 0);
    k_scatter<<<BB * MM, 128>>>(out);
}